// round 9
// baseline (speedup 1.0000x reference)
#include <cuda_runtime.h>

// BKT_RNN: B=8192, T=2048, H=4, X=1.
// R9: two-pass decoupling.
//  Pass 1 (k_h): the only truly sequential part — the 4-unit h recurrence.
//    1 thread/row, no shuffles, ~36 instr/step, chain ~48cyc. Streams h_t to
//    a warp-interleaved scratch ([rowblk][t][lane]) -> 512B-coalesced stores.
//  Pass 2 (k_scan): everything else is parallel over T. 8192 warps. The
//    latent recurrence lat' = (1-l-f)*lat + l is an affine map -> 32-wide
//    Hillis-Steele scan per warp. p-sigmoids computed row-coalesced, coefs
//    transposed through double-buffered smem.

#define TT 2048
#define BB 8192
#define NBLK2 (BB / 32)   // 256 blocks in each pass

typedef unsigned long long u64;

__device__ float4   g_h[(size_t)BB * TT];   // 268MB scratch, interleaved
__device__ float    g_part[NBLK2];
__device__ unsigned g_done = 0;

__device__ __forceinline__ float ex2f(float v) {
    float r; asm("ex2.approx.f32 %0, %1;" : "=f"(r) : "f"(v)); return r;
}
__device__ __forceinline__ float rcpf(float v) {
    float r; asm("rcp.approx.f32 %0, %1;" : "=f"(r) : "f"(v)); return r;
}
__device__ __forceinline__ float lg2f(float v) {
    float r; asm("lg2.approx.f32 %0, %1;" : "=f"(r) : "f"(v)); return r;
}

// ---------------- Pass 1: h recurrence ----------------
__global__ void __launch_bounds__(32) k_h(
    const float* __restrict__ x,  const float* __restrict__ Wxh,
    const float* __restrict__ Whh, const float* __restrict__ bh)
{
    const int lane   = threadIdx.x;
    const int rowblk = blockIdx.x;
    const int row    = rowblk * 32 + lane;

    // Weights pre-scaled by -log2(e): sigmoid(z) = rcp(1 + ex2(z')).
    const float NL2E = -1.4426950408889634f;
    float W[4][4], bh4[4], wx[4];
    #pragma unroll
    for (int j = 0; j < 4; j++) {
        bh4[j] = NL2E * __ldg(bh  + j);
        wx[j]  = NL2E * __ldg(Wxh + j);
        #pragma unroll
        for (int i = 0; i < 4; i++)
            W[i][j] = NL2E * __ldg(Whh + i * 4 + j);
    }

    float h0 = 0.f, h1 = 0.f, h2 = 0.f, h3 = 0.f;

    const float4* xp = (const float4*)(x + (size_t)row * TT);
    float4* hp = g_h + (size_t)rowblk * (TT * 32);

    float4 xa = __ldcs(xp + 0), xb = __ldcs(xp + 1);

    const int NCHUNK = TT / 8;
    for (int c = 0; c < NCHUNK; ++c) {
        float xv[8] = {xa.x, xa.y, xa.z, xa.w, xb.x, xb.y, xb.z, xb.w};
        if (c + 1 < NCHUNK) {
            xa = __ldcs(xp + 2 * c + 2); xb = __ldcs(xp + 2 * c + 3);
        }

        float4 hb[8];
        #pragma unroll
        for (int k = 0; k < 8; k++) {
            hb[k] = make_float4(h0, h1, h2, h3);   // state ENTERING step
            const float xt = xv[k];
            float n[4];
            #pragma unroll
            for (int j = 0; j < 4; j++) {
                const float u = fmaf(h1, W[1][j],
                                 fmaf(h0, W[0][j], fmaf(xt, wx[j], bh4[j])));
                const float v = fmaf(h3, W[3][j], h2 * W[2][j]);
                n[j] = u + v;
            }
            h0 = rcpf(1.f + ex2f(n[0]));
            h1 = rcpf(1.f + ex2f(n[1]));
            h2 = rcpf(1.f + ex2f(n[2]));
            h3 = rcpf(1.f + ex2f(n[3]));
        }

        // Coalesced interleaved stores: [t][lane], 512B per warp-op.
        #pragma unroll
        for (int k = 0; k < 8; k++)
            __stcs(hp + (size_t)(c * 8 + k) * 32 + lane, hb[k]);
    }
}

// ---------------- Pass 2: p-sigmoids + affine scan ----------------
__global__ void __launch_bounds__(1024) k_scan(
    const float* __restrict__ y,  const float* __restrict__ Wy,
    const float* __restrict__ by, const float* __restrict__ prior,
    float* __restrict__ corrects, float* __restrict__ latents,
    float* __restrict__ loss)
{
    const unsigned FULL = 0xffffffffu;
    const int tid    = threadIdx.x;
    const int w      = tid >> 5;     // warp 0..31 (= timestep slot / row)
    const int lane   = tid & 31;
    const int rowblk = blockIdx.x;

    __shared__ float4 sm[2][32][33];          // [buf][t-slot][row-lane]
    __shared__ float  sred[32];

    const float NL2E = -1.4426950408889634f;
    float A[4][4], by4[4];
    #pragma unroll
    for (int j = 0; j < 4; j++) {
        by4[j] = NL2E * __ldg(by + j);
        #pragma unroll
        for (int i = 0; i < 4; i++)
            A[i][j] = NL2E * __ldg(Wy + i * 4 + j);
    }

    const float4* hp = g_h + (size_t)rowblk * (TT * 32);
    const int myrow = rowblk * 32 + w;        // row this warp scans
    float lat  = __ldg(prior);                // latent entering current tile
    float lsum = 0.f, prod = 1.f;

    const int NIT = TT / 32;                  // 64 tiles
    for (int it = 0; it < NIT; ++it) {
        const int tbase = it * 32;
        const int buf   = it & 1;

        // --- produce coefs for (t = tbase+w, row = rowblk*32+lane) ---
        const float4 hv = __ldcs(hp + (size_t)(tbase + w) * 32 + lane);
        float p[4];
        #pragma unroll
        for (int j = 0; j < 4; j++) {
            const float u = fmaf(hv.y, A[1][j], fmaf(hv.x, A[0][j], by4[j]));
            const float v = fmaf(hv.z, A[2][j], hv.w * A[3][j]);
            p[j] = rcpf(1.f + ex2f(u + v));
        }
        // (cl, bl, cg, bg): lat' = cl*lat + bl ; correct = cg*lat + bg
        sm[buf][w][lane] = make_float4(1.f - p[0] - p[1], p[0],
                                       1.f - p[2] - p[3], p[2]);
        __syncthreads();

        // --- scan row `myrow`, t = tbase + lane ---
        const float4 cf = sm[buf][lane][w];
        float C = cf.x, Bv = cf.y;
        #pragma unroll
        for (int off = 1; off < 32; off <<= 1) {
            const float c2 = __shfl_up_sync(FULL, C,  off);
            const float b2 = __shfl_up_sync(FULL, Bv, off);
            if (lane >= off) { Bv = fmaf(b2, C, Bv); C *= c2; }
        }
        float Cex = __shfl_up_sync(FULL, C,  1);
        float Bex = __shfl_up_sync(FULL, Bv, 1);
        if (lane == 0) { Cex = 1.f; Bex = 0.f; }

        const float Lent = fmaf(lat, Cex, Bex);   // latent entering step t
        const float Laft = fmaf(lat, C,   Bv);    // latent after step t
        const float corr = fmaf(Lent, cf.z, cf.w);

        const int t = tbase + lane;
        __stcs(corrects + (size_t)myrow * TT + t, corr);
        __stcs(latents  + (size_t)myrow * TT + t, Laft);

        const float yv = __ldcs(y + (size_t)myrow * TT + t);
        const float cc = fminf(fmaxf(corr, 1e-7f), 1.0f - 1e-7f);
        prod *= (yv != 0.f) ? cc : (1.f - cc);
        if ((it & 3) == 3) { lsum += lg2f(prod); prod = 1.f; }

        lat = __shfl_sync(FULL, Laft, 31);        // carry to next tile
    }

    // --- loss reduction: warp -> block -> global ticket ---
    #pragma unroll
    for (int o = 16; o > 0; o >>= 1)
        lsum += __shfl_xor_sync(FULL, lsum, o);
    if (lane == 0) sred[w] = lsum;
    __syncthreads();
    if (w == 0) {
        float v = sred[lane];
        #pragma unroll
        for (int o = 16; o > 0; o >>= 1)
            v += __shfl_xor_sync(FULL, v, o);
        if (lane == 0) g_part[rowblk] = v;
    }
    __threadfence();

    __shared__ unsigned s_tkt;
    if (tid == 0) s_tkt = atomicAdd(&g_done, 1u);
    __syncthreads();
    if (s_tkt == NBLK2 - 1 && w == 0) {
        double acc = 0.0;
        for (int i = lane; i < NBLK2; i += 32)
            acc += (double)g_part[i];
        #pragma unroll
        for (int o = 16; o > 0; o >>= 1)
            acc += __shfl_xor_sync(FULL, acc, o);
        if (lane == 0) {
            loss[0] = (float)(-0.6931471805599453 * acc /
                              ((double)BB * (double)TT));
            g_done = 0;   // re-arm for graph replay
        }
    }
}

extern "C" void kernel_launch(void* const* d_in, const int* in_sizes, int n_in,
                              void* d_out, int out_size) {
    const float* x     = (const float*)d_in[0];
    const float* y     = (const float*)d_in[1];
    const float* Wxh   = (const float*)d_in[2];
    const float* Whh   = (const float*)d_in[3];
    const float* bh    = (const float*)d_in[4];
    const float* Wy    = (const float*)d_in[5];
    const float* by    = (const float*)d_in[6];
    const float* prior = (const float*)d_in[7];

    float* corrects = (float*)d_out;
    float* latents  = (float*)d_out + (size_t)BB * TT;
    float* loss     = (float*)d_out + 2 * (size_t)BB * TT;

    k_h<<<NBLK2, 32>>>(x, Wxh, Whh, bh);
    k_scan<<<NBLK2, 1024>>>(y, Wy, by, prior, corrects, latents, loss);
}

// round 10
// speedup vs baseline: 2.1748x; 2.1748x over previous
#include <cuda_runtime.h>

// BKT_RNN: B=8192, T=2048, H=4, X=1.
// R10: R7 frame (4 lanes/row, 1024 one-warp blocks, closed-form BKT latent,
// fused loss) with the per-step dependency DAG shortened:
//  - h-recurrence sigmoid via tanh.approx (1 MUFU): sigma(z)=0.5+0.5*tanh(z/2),
//    carrying tau=tanh state; the affine 0.5+0.5*tau fold is absorbed into
//    weights/biases at setup -> MUFU result feeds the shuffles directly.
//  - h all-gather via 3 PARALLEL scalar shfl_xor (1/2/3) instead of the
//    serial shfl->pack->shfl (same MIO count, ~30cyc shorter chain).
//  - p-sigmoids stay exact (ex2+rcp), off the critical cycle.

#define TT 2048
#define BB 8192
#define NBLK (BB / 8)   // 1024 one-warp blocks

__device__ float    g_part[NBLK];
__device__ unsigned g_done = 0;

__device__ __forceinline__ float ex2f(float v) {
    float r; asm("ex2.approx.f32 %0, %1;" : "=f"(r) : "f"(v)); return r;
}
__device__ __forceinline__ float rcpf(float v) {
    float r; asm("rcp.approx.f32 %0, %1;" : "=f"(r) : "f"(v)); return r;
}
__device__ __forceinline__ float lg2f(float v) {
    float r; asm("lg2.approx.f32 %0, %1;" : "=f"(r) : "f"(v)); return r;
}
__device__ __forceinline__ float tanhf_a(float v) {
    float r; asm("tanh.approx.f32 %0, %1;" : "=f"(r) : "f"(v)); return r;
}

__global__ void __launch_bounds__(32) k_bkt(
    const float* __restrict__ x,   const float* __restrict__ y,
    const float* __restrict__ Wxh, const float* __restrict__ Whh,
    const float* __restrict__ bh,  const float* __restrict__ Wy,
    const float* __restrict__ by,  const float* __restrict__ prior,
    float* __restrict__ corrects,  float* __restrict__ latents,
    float* __restrict__ loss)
{
    const unsigned FULL = 0xffffffffu;
    const int lane = threadIdx.x;
    const int j = lane & 3;                    // unit index within row
    const int b = blockIdx.x * 8 + (lane >> 2);

    // State carried: tau_j = tanh(zh_j/2), h_j = 0.5 + 0.5*tau_j.
    // h-dot in tau form:  zh/2 = 0.5*x*Wxh[j] + sum_i tau_i*(Whh[i][j]/4)
    //                           + 0.5*bh[j] + 0.25*sum_i Whh[i][j]
    // p-dot in tau form:  zp   = sum_i tau_i*(Wy[i][j]/2)
    //                           + by[j] + 0.5*sum_i Wy[i][j]   (then *-log2e)
    // Rows permuted to gather order [j, j^1, j^2, j^3].
    const float NL2E = -1.4426950408889634f;
    float Ac[4], Wc[4];
    float sumWy = 0.f, sumWh = 0.f;
    #pragma unroll
    for (int m = 0; m < 4; m++) {
        const int src = j ^ m;
        const float wy = __ldg(Wy  + src * 4 + j);
        const float wh = __ldg(Whh + src * 4 + j);
        Ac[m] = NL2E * 0.5f * wy;
        Wc[m] = 0.25f * wh;
        sumWy += wy;
        sumWh += wh;
    }
    const float bias_p = NL2E * (__ldg(by + j) + 0.5f * sumWy);
    const float bias_h = 0.5f * __ldg(bh + j) + 0.25f * sumWh;
    const float xcoef  = 0.5f * __ldg(Wxh + j);

    float tau  = -1.f;             // h = 0  ->  tau = -1
    float lat  = __ldg(prior);     // authoritative on lane 0 of each group
    float lsum = 0.f;
    const bool odd = (lane & 1) != 0;
    const bool hi2 = (lane & 2) != 0;   // lanes 2,3 produce `correct`

    const float4* xp = (const float4*)(x + (size_t)b * TT);
    const float4* yp = (const float4*)(y + (size_t)b * TT);
    // Lanes 0/1 write latents, lanes 2/3 write corrects.
    float4* op = (float4*)((hi2 ? corrects : latents) + (size_t)b * TT);

    // Prime pipeline (chunk 0 = 8 timesteps).
    float4 xa = __ldcs(xp + 0), xb = __ldcs(xp + 1);
    float4 ya = __ldcs(yp + 0), yb = __ldcs(yp + 1);

    const int NCHUNK = TT / 8;
    for (int c = 0; c < NCHUNK; ++c) {
        float xv[8] = {xa.x, xa.y, xa.z, xa.w, xb.x, xb.y, xb.z, xb.w};
        float yv[8] = {ya.x, ya.y, ya.z, ya.w, yb.x, yb.y, yb.z, yb.w};

        if (c + 1 < NCHUNK) {   // prefetch next chunk under compute
            xa = __ldcs(xp + 2 * c + 2); xb = __ldcs(xp + 2 * c + 3);
            ya = __ldcs(yp + 2 * c + 2); yb = __ldcs(yp + 2 * c + 3);
        }

        float rb[8];
        float prod = 1.f;

        #pragma unroll
        for (int k = 0; k < 8; k++) {
            // ---- h all-gather: 3 PARALLEL shuffles (all depend only on tau)
            const float t1 = __shfl_xor_sync(FULL, tau, 1);
            const float t2 = __shfl_xor_sync(FULL, tau, 2);
            const float t3 = __shfl_xor_sync(FULL, tau, 3);

            // ---- h-dot (tree, late-arriving values shallow) + tanh ----
            const float preh = fmaf(xv[k], xcoef, bias_h);  // off-chain
            const float zhu  = fmaf(t1, Wc[1], fmaf(tau, Wc[0], preh));
            const float zhv  = fmaf(t2, Wc[2], t3 * Wc[3]);
            const float ntau = tanhf_a(zhu + zhv);

            // ---- p-dot + exact sigmoid (off the critical cycle) ----
            const float zpu = fmaf(t1, Ac[1], fmaf(tau, Ac[0], bias_p));
            const float zpv = fmaf(t2, Ac[2], t3 * Ac[3]);
            const float pj  = rcpf(1.f + ex2f(zpu + zpv));

            tau = ntau;

            // ---- latent / correct: unified FMA form ----
            // lanes 0,1: (l,f) -> res = l + lat*(1-l-f) = lat'
            // lanes 2,3: (g,s) -> res = g + lat*(1-g-s) = correct
            const float po   = __shfl_xor_sync(FULL, pj, 1);
            const float coef = 1.f - pj - po;
            const float base = odd ? po : pj;
            const float latc = __shfl_sync(FULL, lat, 0, 4);  // old latent
            const float res  = fmaf(latc, coef, base);
            lat = res;                 // only lane 0's copy is ever read
            rb[k] = res;

            // ---- loss (lanes 2,3; y in {0,1} -> one factor) ----
            const float cc = fminf(fmaxf(res, 1e-7f), 1.0f - 1e-7f);
            prod *= (yv[k] != 0.f) ? cc : (1.f - cc);
            if ((k & 3) == 3) {
                lsum += hi2 ? lg2f(prod) : 0.f;
                prod = 1.f;
            }
        }

        // Even lanes store elements 0..3, odd lanes 4..7 of their series.
        const float4 v = odd ? make_float4(rb[4], rb[5], rb[6], rb[7])
                             : make_float4(rb[0], rb[1], rb[2], rb[3]);
        __stcs(op + 2 * c + (odd ? 1 : 0), v);
    }

    // Warp reduce (each row counted 2x: lanes 2 and 3) -> per-block slot.
    #pragma unroll
    for (int o = 16; o > 0; o >>= 1)
        lsum += __shfl_xor_sync(FULL, lsum, o);
    if (lane == 0)
        g_part[blockIdx.x] = lsum;
    __threadfence();

    // Last-block-done reduction (fused finalize).
    unsigned ticket = 0;
    if (lane == 0) ticket = atomicAdd(&g_done, 1u);
    ticket = __shfl_sync(FULL, ticket, 0);
    if (ticket == NBLK - 1) {
        double acc = 0.0;
        for (int i = lane; i < NBLK; i += 32)
            acc += (double)g_part[i];
        #pragma unroll
        for (int o = 16; o > 0; o >>= 1)
            acc += __shfl_xor_sync(FULL, acc, o);
        if (lane == 0) {
            loss[0] = (float)(-0.6931471805599453 * acc /
                              (2.0 * (double)BB * (double)TT));
            g_done = 0;   // re-arm for the next graph replay
        }
    }
}

extern "C" void kernel_launch(void* const* d_in, const int* in_sizes, int n_in,
                              void* d_out, int out_size) {
    const float* x     = (const float*)d_in[0];
    const float* y     = (const float*)d_in[1];
    const float* Wxh   = (const float*)d_in[2];
    const float* Whh   = (const float*)d_in[3];
    const float* bh    = (const float*)d_in[4];
    const float* Wy    = (const float*)d_in[5];
    const float* by    = (const float*)d_in[6];
    const float* prior = (const float*)d_in[7];

    float* corrects = (float*)d_out;
    float* latents  = (float*)d_out + (size_t)BB * TT;
    float* loss     = (float*)d_out + 2 * (size_t)BB * TT;

    k_bkt<<<NBLK, 32>>>(x, y, Wxh, Whh, bh, Wy, by, prior,
                        corrects, latents, loss);
}

// round 11
// speedup vs baseline: 2.5125x; 1.1553x over previous
#include <cuda_runtime.h>

// BKT_RNN: B=8192, T=2048, H=4, X=1.
// R11: shuffle-free recurrent cycle. Each lane REDUNDANTLY computes all four
// h units via packed fma.rn.f32x2 dots + 4x tanh.approx (no exchange on the
// tau cycle). p-sigmoids via tanh.approx too; the 0.5+0.5*tau affine folds
// into the latent/correct FMA coefficients. Lanes 0/1 carry the latent
// locally (4-cyc cycle); lanes 2/3 receive it by off-cycle shfl.
// R10 frame otherwise: 4 lanes/row, 8 rows/warp, 1024 one-warp blocks,
// chunked coalesced I/O, fused last-block loss.

#define TT 2048
#define BB 8192
#define NBLK (BB / 8)   // 1024 one-warp blocks

typedef unsigned long long u64;

__device__ float    g_part[NBLK];
__device__ unsigned g_done = 0;

__device__ __forceinline__ float lg2f(float v) {
    float r; asm("lg2.approx.f32 %0, %1;" : "=f"(r) : "f"(v)); return r;
}
__device__ __forceinline__ float tanhf_a(float v) {
    float r; asm("tanh.approx.f32 %0, %1;" : "=f"(r) : "f"(v)); return r;
}
__device__ __forceinline__ u64 pack2(float lo, float hi) {
    u64 r; asm("mov.b64 %0, {%1, %2};" : "=l"(r) : "f"(lo), "f"(hi)); return r;
}
__device__ __forceinline__ void unpack2(u64 v, float& lo, float& hi) {
    asm("mov.b64 {%0, %1}, %2;" : "=f"(lo), "=f"(hi) : "l"(v));
}
__device__ __forceinline__ u64 fma2(u64 a, u64 b, u64 c) {
    u64 d; asm("fma.rn.f32x2 %0, %1, %2, %3;" : "=l"(d) : "l"(a), "l"(b), "l"(c));
    return d;
}
__device__ __forceinline__ u64 mul2(u64 a, u64 b) {
    u64 d; asm("mul.rn.f32x2 %0, %1, %2;" : "=l"(d) : "l"(a), "l"(b));
    return d;
}
__device__ __forceinline__ u64 add2(u64 a, u64 b) {
    u64 d; asm("add.rn.f32x2 %0, %1, %2;" : "=l"(d) : "l"(a), "l"(b));
    return d;
}

__global__ void __launch_bounds__(32) k_bkt(
    const float* __restrict__ x,   const float* __restrict__ y,
    const float* __restrict__ Wxh, const float* __restrict__ Whh,
    const float* __restrict__ bh,  const float* __restrict__ Wy,
    const float* __restrict__ by,  const float* __restrict__ prior,
    float* __restrict__ corrects,  float* __restrict__ latents,
    float* __restrict__ loss)
{
    const unsigned FULL = 0xffffffffu;
    const int lane = threadIdx.x;
    const int j = lane & 3;                    // p-unit owned by this lane
    const int b = blockIdx.x * 8 + (lane >> 2);

    // ---- tau-form setup. State: tau_i = tanh(zh_i/2), h_i = 0.5+0.5 tau_i.
    // zh_i/2 = 0.5 x Wxh[i] + sum_m tau_m (Whh[m][i]/4)
    //          + (0.5 bh[i] + 0.25 sum_m Whh[m][i])
    // zp_j/2 = sum_m tau_m (Wy[m][j]/4) + (0.5 by[j] + 0.25 sum_m Wy[m][j])
    float wh[4][4];         // Whh[m][i]/4
    float pre_b[4];         // 0.5 bh[i] + 0.25 sum_m Whh[m][i]
    float xw[4];            // 0.5 Wxh[i]
    #pragma unroll
    for (int i = 0; i < 4; i++) {
        float s = 0.f;
        #pragma unroll
        for (int m = 0; m < 4; m++) {
            const float w = __ldg(Whh + m * 4 + i);
            wh[m][i] = 0.25f * w;
            s += w;
        }
        pre_b[i] = 0.5f * __ldg(bh + i) + 0.25f * s;
        xw[i]    = 0.5f * __ldg(Wxh + i);
    }
    // Packed h weights: columns (0,1) and (2,3).
    u64 W01[4], W23[4];
    #pragma unroll
    for (int m = 0; m < 4; m++) {
        W01[m] = pack2(wh[m][0], wh[m][1]);
        W23[m] = pack2(wh[m][2], wh[m][3]);
    }
    const u64 B01  = pack2(pre_b[0], pre_b[1]);
    const u64 B23  = pack2(pre_b[2], pre_b[3]);
    const u64 XW01 = pack2(xw[0], xw[1]);
    const u64 XW23 = pack2(xw[2], xw[3]);

    // p weights (own column j only).
    float Pc[4]; float sWy = 0.f;
    #pragma unroll
    for (int m = 0; m < 4; m++) {
        const float w = __ldg(Wy + m * 4 + j);
        Pc[m] = 0.25f * w;
        sWy  += w;
    }
    const float bias_p = 0.5f * __ldg(by + j) + 0.25f * sWy;

    float tau0 = -1.f, tau1 = -1.f, tau2 = -1.f, tau3 = -1.f;  // h = 0
    float lat  = __ldg(prior);     // maintained locally on lanes 0,1
    float lsum = 0.f;
    const bool odd = (lane & 1) != 0;
    const bool hi2 = (lane & 2) != 0;   // lanes 2,3 -> correct series

    const float4* xp = (const float4*)(x + (size_t)b * TT);
    const float4* yp = (const float4*)(y + (size_t)b * TT);
    float4* op = (float4*)((hi2 ? corrects : latents) + (size_t)b * TT);

    float4 xa = __ldcs(xp + 0), xb = __ldcs(xp + 1);
    float4 ya = __ldcs(yp + 0), yb = __ldcs(yp + 1);

    const int NCHUNK = TT / 8;
    for (int c = 0; c < NCHUNK; ++c) {
        float xv[8] = {xa.x, xa.y, xa.z, xa.w, xb.x, xb.y, xb.z, xb.w};
        float yv[8] = {ya.x, ya.y, ya.z, ya.w, yb.x, yb.y, yb.z, yb.w};

        if (c + 1 < NCHUNK) {
            xa = __ldcs(xp + 2 * c + 2); xb = __ldcs(xp + 2 * c + 3);
            ya = __ldcs(yp + 2 * c + 2); yb = __ldcs(yp + 2 * c + 3);
        }

        float rb[8];
        float prod = 1.f;

        #pragma unroll
        for (int k = 0; k < 8; k++) {
            // ---- x preamble (off the recurrent cycle) ----
            const u64 X2   = pack2(xv[k], xv[k]);
            const u64 PRE01 = fma2(X2, XW01, B01);
            const u64 PRE23 = fma2(X2, XW23, B23);

            // ---- duplicate taus for packed dots ----
            const u64 T0 = pack2(tau0, tau0);
            const u64 T1 = pack2(tau1, tau1);
            const u64 T2 = pack2(tau2, tau2);
            const u64 T3 = pack2(tau3, tau3);

            // ---- packed h pre-activations (all 4 units, this lane) ----
            const u64 Z01 = add2(fma2(T1, W01[1], fma2(T0, W01[0], PRE01)),
                                 fma2(T3, W01[3], mul2(T2, W01[2])));
            const u64 Z23 = add2(fma2(T1, W23[1], fma2(T0, W23[0], PRE23)),
                                 fma2(T3, W23[3], mul2(T2, W23[2])));

            // ---- own p pre-activation (OLD taus) ----
            const float zp = fmaf(tau1, Pc[1], fmaf(tau0, Pc[0], bias_p)) +
                             fmaf(tau3, Pc[3], tau2 * Pc[2]);
            const float taup = tanhf_a(zp);     // p_j = 0.5 + 0.5*taup

            // ---- advance tau (4 independent tanh) ----
            float z0, z1, z2, z3;
            unpack2(Z01, z0, z1);
            unpack2(Z23, z2, z3);
            tau0 = tanhf_a(z0);
            tau1 = tanhf_a(z1);
            tau2 = tanhf_a(z2);
            tau3 = tanhf_a(z3);

            // ---- latent / correct (tau-form, unified) ----
            // lanes 0,1: (l,f): lat' = base + lat*coef,
            //   base = 0.5+0.5*tau_l, coef = -0.5*(tau_l+tau_f)
            // lanes 2,3: (g,s): correct likewise with (g,s) and old lat.
            const float taupo = __shfl_xor_sync(FULL, taup, 1);
            const float coef  = -0.5f * (taup + taupo);
            const float btau  = odd ? taupo : taup;
            const float base  = fmaf(0.5f, btau, 0.5f);
            const float latc  = __shfl_sync(FULL, lat, 0, 4); // for lanes 2,3
            const float res   = fmaf(hi2 ? latc : lat, coef, base);
            lat = res;                // meaningful on lanes 0,1
            rb[k] = res;

            // ---- loss (lanes 2,3) ----
            const float cc = fminf(fmaxf(res, 1e-7f), 1.0f - 1e-7f);
            prod *= (yv[k] != 0.f) ? cc : (1.f - cc);
            if ((k & 3) == 3) {
                lsum += hi2 ? lg2f(prod) : 0.f;
                prod = 1.f;
            }
        }

        const float4 v = odd ? make_float4(rb[4], rb[5], rb[6], rb[7])
                             : make_float4(rb[0], rb[1], rb[2], rb[3]);
        __stcs(op + 2 * c + (odd ? 1 : 0), v);
    }

    // Warp reduce (each row counted 2x: lanes 2,3) -> per-block slot.
    #pragma unroll
    for (int o = 16; o > 0; o >>= 1)
        lsum += __shfl_xor_sync(FULL, lsum, o);
    if (lane == 0)
        g_part[blockIdx.x] = lsum;
    __threadfence();

    // Last-block-done loss finalize.
    unsigned ticket = 0;
    if (lane == 0) ticket = atomicAdd(&g_done, 1u);
    ticket = __shfl_sync(FULL, ticket, 0);
    if (ticket == NBLK - 1) {
        double acc = 0.0;
        for (int i = lane; i < NBLK; i += 32)
            acc += (double)g_part[i];
        #pragma unroll
        for (int o = 16; o > 0; o >>= 1)
            acc += __shfl_xor_sync(FULL, acc, o);
        if (lane == 0) {
            loss[0] = (float)(-0.6931471805599453 * acc /
                              (2.0 * (double)BB * (double)TT));
            g_done = 0;   // re-arm for graph replay
        }
    }
}

extern "C" void kernel_launch(void* const* d_in, const int* in_sizes, int n_in,
                              void* d_out, int out_size) {
    const float* x     = (const float*)d_in[0];
    const float* y     = (const float*)d_in[1];
    const float* Wxh   = (const float*)d_in[2];
    const float* Whh   = (const float*)d_in[3];
    const float* bh    = (const float*)d_in[4];
    const float* Wy    = (const float*)d_in[5];
    const float* by    = (const float*)d_in[6];
    const float* prior = (const float*)d_in[7];

    float* corrects = (float*)d_out;
    float* latents  = (float*)d_out + (size_t)BB * TT;
    float* loss     = (float*)d_out + 2 * (size_t)BB * TT;

    k_bkt<<<NBLK, 32>>>(x, y, Wxh, Whh, bh, Wy, by, prior,
                        corrects, latents, loss);
}